// round 8
// baseline (speedup 1.0000x reference)
#include <cuda_runtime.h>
#include <cstdint>
#include <math.h>

#define Bsz 4096
#define Asz 4096
#define Hsz 768
#define Lsz 4
#define G3H (3 * Hsz)   // 2304

#define GUMBEL_PARTITIONABLE 1

// ======================= device scratch ===================================
__device__ float d_wih_hi[(size_t)G3H * Hsz];
__device__ float d_wih_lo[(size_t)G3H * Hsz];
__device__ float d_whh_hi[(size_t)G3H * Hsz];
__device__ float d_whh_lo[(size_t)G3H * Hsz];
__device__ float d_hw_hi[(size_t)Asz * Hsz];
__device__ float d_hw_lo[(size_t)Asz * Hsz];
__device__ float d_a_hi[(size_t)Bsz * Hsz];   // A-side split (cls / ae_w / h)
__device__ float d_a_lo[(size_t)Bsz * Hsz];
__device__ float d_Gcls[(size_t)Bsz * G3H];
__device__ float d_AEp[(size_t)Asz * G3H];
__device__ float d_gh[(size_t)Bsz * G3H];
__device__ float d_h[(size_t)Bsz * Hsz];
__device__ float d_logits[(size_t)Bsz * Asz];
__device__ unsigned int d_mask[(size_t)Bsz * Asz / 32];
__device__ int d_idx[Lsz * Bsz];

// ======================= threefry2x32 =====================================
__host__ __device__ __forceinline__ void threefry2x32(
    unsigned int k0, unsigned int k1, unsigned int x0, unsigned int x1,
    unsigned int& o0, unsigned int& o1)
{
    unsigned int ks0 = k0, ks1 = k1, ks2 = k0 ^ k1 ^ 0x1BD11BDAu;
    x0 += ks0; x1 += ks1;
#define TF_RND(r) { x0 += x1; x1 = (x1 << (r)) | (x1 >> (32 - (r))); x1 ^= x0; }
    TF_RND(13) TF_RND(15) TF_RND(26) TF_RND(6)
    x0 += ks1; x1 += ks2 + 1u;
    TF_RND(17) TF_RND(29) TF_RND(16) TF_RND(24)
    x0 += ks2; x1 += ks0 + 2u;
    TF_RND(13) TF_RND(15) TF_RND(26) TF_RND(6)
    x0 += ks0; x1 += ks1 + 3u;
    TF_RND(17) TF_RND(29) TF_RND(16) TF_RND(24)
    x0 += ks1; x1 += ks2 + 4u;
    TF_RND(13) TF_RND(15) TF_RND(26) TF_RND(6)
    x0 += ks2; x1 += ks0 + 5u;
#undef TF_RND
    o0 = x0; o1 = x1;
}

// ======================= split helper =====================================
__device__ __forceinline__ uint32_t f2tf(float x) {
    uint32_t r; asm("cvt.rna.tf32.f32 %0, %1;" : "=r"(r) : "f"(x));
    return r;
}
__device__ __forceinline__ void split_hl_f(float x, float& hi, float& lo) {
    uint32_t h = __float_as_uint(x) & 0xFFFFE000u;
    hi = __uint_as_float(h);
    lo = __uint_as_float(f2tf(x - hi));
}

// ======================= tf32x3 mma.sync GEMM (pre-split) =================
// C[M,N] = A[M,K] @ B[N,K]^T (+bias).  A/B given as tf32-valued fp32 hi/lo.
// Inner loop: pure LDS + HMMA (no split ALU).  Tile 128x128, BK=16,
// 2-stage cp.async pipeline, 8 warps, dynamic smem 80KB, 2 CTAs/SM.
#define BM 128
#define BN 128
#define BKc 16
#define LDT 20                      // smem row stride in floats
#define REG_SZ (2 * BM * LDT * 4)   // one region: [2][128][20] floats = 20480 B
#define SMO_AH 0
#define SMO_AL (REG_SZ)
#define SMO_BH (2 * REG_SZ)
#define SMO_BL (3 * REG_SZ)
#define GEMM_SMEM (4 * REG_SZ)      // 81920 B

#define CP_ASYNC16(dst_u32, src_ptr) \
    asm volatile("cp.async.cg.shared.global [%0], [%1], 16;" :: "r"(dst_u32), "l"(src_ptr) : "memory")
#define CP_COMMIT() asm volatile("cp.async.commit_group;" ::: "memory")
#define CP_WAIT(n)  asm volatile("cp.async.wait_group %0;" :: "n"(n) : "memory")

#define MMA_TF32(c, a, b) \
    asm volatile("mma.sync.aligned.m16n8k8.row.col.f32.tf32.tf32.f32 " \
        "{%0,%1,%2,%3}, {%4,%5,%6,%7}, {%8,%9}, {%0,%1,%2,%3};" \
        : "+f"((c)[0]), "+f"((c)[1]), "+f"((c)[2]), "+f"((c)[3]) \
        : "r"((a)[0]), "r"((a)[1]), "r"((a)[2]), "r"((a)[3]), \
          "r"((b)[0]), "r"((b)[1]))

__global__ void __launch_bounds__(256, 2)
gemm_tf32x3(const float* __restrict__ Ahi, const float* __restrict__ Alo,
            const float* __restrict__ Bhi, const float* __restrict__ Blo,
            const float* __restrict__ bias, float* __restrict__ C,
            int M, int N, int K)
{
    extern __shared__ char smraw[];
    float* SAh = (float*)(smraw + SMO_AH);
    float* SAl = (float*)(smraw + SMO_AL);
    float* SBh = (float*)(smraw + SMO_BH);
    float* SBl = (float*)(smraw + SMO_BL);

    const int tid = threadIdx.x;
    const int wid = tid >> 5, lane = tid & 31;
    const int wm = wid >> 1;           // 0..3
    const int wn = wid & 1;            // 0..1
    const int g = lane >> 2;           // 0..7
    const int tg = lane & 3;           // 0..3
    const int bm = blockIdx.y * BM;
    const int bn = blockIdx.x * BN;
    const int NC = K / BKc;            // 48

    uint32_t smb;
    asm("{ .reg .u64 t; cvta.to.shared.u64 t, %1; cvt.u32.u64 %0, t; }"
        : "=r"(smb) : "l"(smraw));

    float acc[2][8][4];
#pragma unroll
    for (int i = 0; i < 2; i++)
#pragma unroll
        for (int j = 0; j < 8; j++)
#pragma unroll
            for (int k = 0; k < 4; k++) acc[i][j][k] = 0.f;

    // per-thread cp.async coords: 512 float4 slots per region, 2 per thread
    const int r_ = tid >> 1;            // 0..127
    const int q_ = (tid & 1) * 2;       // 0 or 2 (two float4 = 8 floats each half-row)

    // ---- load chunk 0 ----
    {
#pragma unroll
        for (int h = 0; h < 2; h++) {   // q_ and q_+1 float4 quads
            int q = q_ + h;             // 0..3
            CP_ASYNC16(smb + SMO_AH + (uint32_t)((0 * BM + r_) * LDT + q * 4) * 4,
                       Ahi + (size_t)(bm + r_) * K + q * 4);
            CP_ASYNC16(smb + SMO_AL + (uint32_t)((0 * BM + r_) * LDT + q * 4) * 4,
                       Alo + (size_t)(bm + r_) * K + q * 4);
            CP_ASYNC16(smb + SMO_BH + (uint32_t)((0 * BN + r_) * LDT + q * 4) * 4,
                       Bhi + (size_t)(bn + r_) * K + q * 4);
            CP_ASYNC16(smb + SMO_BL + (uint32_t)((0 * BN + r_) * LDT + q * 4) * 4,
                       Blo + (size_t)(bn + r_) * K + q * 4);
        }
        CP_COMMIT();
    }

    for (int c = 0; c < NC; ++c) {
        if (c + 1 < NC) {
            const int k0 = (c + 1) * BKc;
            const int nb = (c + 1) & 1;
#pragma unroll
            for (int h = 0; h < 2; h++) {
                int q = q_ + h;
                CP_ASYNC16(smb + SMO_AH + (uint32_t)((nb * BM + r_) * LDT + q * 4) * 4,
                           Ahi + (size_t)(bm + r_) * K + k0 + q * 4);
                CP_ASYNC16(smb + SMO_AL + (uint32_t)((nb * BM + r_) * LDT + q * 4) * 4,
                           Alo + (size_t)(bm + r_) * K + k0 + q * 4);
                CP_ASYNC16(smb + SMO_BH + (uint32_t)((nb * BN + r_) * LDT + q * 4) * 4,
                           Bhi + (size_t)(bn + r_) * K + k0 + q * 4);
                CP_ASYNC16(smb + SMO_BL + (uint32_t)((nb * BN + r_) * LDT + q * 4) * 4,
                           Blo + (size_t)(bn + r_) * K + k0 + q * 4);
            }
            CP_COMMIT();
            CP_WAIT(1);
        } else {
            CP_WAIT(0);
        }
        __syncthreads();

        const int cbo = (c & 1) * BM * LDT;
#pragma unroll
        for (int ks = 0; ks < 2; ks++) {
            const int kk = ks * 8;
            uint32_t ahi[2][4], alo[2][4];
#pragma unroll
            for (int mt = 0; mt < 2; mt++) {
                const int r0 = wm * 32 + mt * 16 + g;
                const int i00 = cbo + r0 * LDT + kk + tg;
                ahi[mt][0] = __float_as_uint(SAh[i00]);
                ahi[mt][1] = __float_as_uint(SAh[i00 + 8 * LDT]);
                ahi[mt][2] = __float_as_uint(SAh[i00 + 4]);
                ahi[mt][3] = __float_as_uint(SAh[i00 + 8 * LDT + 4]);
                alo[mt][0] = __float_as_uint(SAl[i00]);
                alo[mt][1] = __float_as_uint(SAl[i00 + 8 * LDT]);
                alo[mt][2] = __float_as_uint(SAl[i00 + 4]);
                alo[mt][3] = __float_as_uint(SAl[i00 + 8 * LDT + 4]);
            }
#pragma unroll
            for (int hb = 0; hb < 2; hb++) {
                uint32_t bhi[4][2], blo[4][2];
#pragma unroll
                for (int nt = 0; nt < 4; nt++) {
                    const int n0 = wn * 64 + (hb * 4 + nt) * 8 + g;
                    const int i0 = cbo + n0 * LDT + kk + tg;
                    bhi[nt][0] = __float_as_uint(SBh[i0]);
                    bhi[nt][1] = __float_as_uint(SBh[i0 + 4]);
                    blo[nt][0] = __float_as_uint(SBl[i0]);
                    blo[nt][1] = __float_as_uint(SBl[i0 + 4]);
                }
#pragma unroll
                for (int mt = 0; mt < 2; mt++)
#pragma unroll
                    for (int nt = 0; nt < 4; nt++)
                        MMA_TF32(acc[mt][hb * 4 + nt], ahi[mt], blo[nt]);
#pragma unroll
                for (int mt = 0; mt < 2; mt++)
#pragma unroll
                    for (int nt = 0; nt < 4; nt++)
                        MMA_TF32(acc[mt][hb * 4 + nt], alo[mt], bhi[nt]);
#pragma unroll
                for (int mt = 0; mt < 2; mt++)
#pragma unroll
                    for (int nt = 0; nt < 4; nt++)
                        MMA_TF32(acc[mt][hb * 4 + nt], ahi[mt], bhi[nt]);
            }
        }
        __syncthreads();
    }

    // ---- epilogue ----
#pragma unroll
    for (int mt = 0; mt < 2; mt++) {
        const int r0 = bm + wm * 32 + mt * 16 + g;
#pragma unroll
        for (int nt = 0; nt < 8; nt++) {
            const int n0 = bn + wn * 64 + nt * 8 + tg * 2;
            float bx = 0.f, by = 0.f;
            if (bias) { bx = bias[n0]; by = bias[n0 + 1]; }
            float2 v0 = make_float2(acc[mt][nt][0] + bx, acc[mt][nt][1] + by);
            float2 v1 = make_float2(acc[mt][nt][2] + bx, acc[mt][nt][3] + by);
            *(float2*)(C + (size_t)r0 * N + n0) = v0;
            *(float2*)(C + (size_t)(r0 + 8) * N + n0) = v1;
        }
    }
}

// ======================= elementwise kernels ==============================
__global__ void split_kernel(const float* __restrict__ src,
                             float* __restrict__ hi, float* __restrict__ lo, int n)
{
    int i = blockIdx.x * blockDim.x + threadIdx.x;
    if (i >= n) return;
    float h, l; split_hl_f(src[i], h, l);
    hi[i] = h; lo[i] = l;
}

__global__ void zero_out_kernel(float4* out, size_t n4)
{
    size_t i = (size_t)blockIdx.x * blockDim.x + threadIdx.x;
    size_t stride = (size_t)gridDim.x * blockDim.x;
    float4 z = make_float4(0.f, 0.f, 0.f, 0.f);
    for (; i < n4; i += stride) out[i] = z;
}

__global__ void init_mask_kernel(const float* __restrict__ x_, int nwords)
{
    int w = blockIdx.x * blockDim.x + threadIdx.x;
    if (w >= nwords) return;
    int b = w >> 7;
    int wa = w & 127;
    const float* xr = x_ + (size_t)b * Asz + wa * 32;
    unsigned int bits = 0;
#pragma unroll
    for (int e = 0; e < 32; e++)
        if (xr[e] != 0.0f) bits |= (1u << e);
    d_mask[w] = bits;
}

// Step 0: h_prev = 0 -> gh = b_hh exactly; h = (1-z)*n.  Writes h + splits.
__global__ void gru_step0_kernel(const float* __restrict__ b_hh, int n)
{
    int i = blockIdx.x * blockDim.x + threadIdx.x;
    if (i >= n) return;
    int b = i / Hsz, k = i - b * Hsz;
    const float* gg = d_Gcls + (size_t)b * G3H;
    float ir = gg[k], iz = gg[Hsz + k], inn = gg[2 * Hsz + k];
    float hr = b_hh[k], hz = b_hh[Hsz + k], hn = b_hh[2 * Hsz + k];
    float r = 1.f / (1.f + expf(-(ir + hr)));
    float z = 1.f / (1.f + expf(-(iz + hz)));
    float nn = tanhf(inn + r * hn);
    float hv = (1.f - z) * nn;
    d_h[i] = hv;
    float h_, l_; split_hl_f(hv, h_, l_);
    d_a_hi[i] = h_; d_a_lo[i] = l_;
}

// Step j>=1: gi = G_cls + AE_proj[idx_{j-1}]; gh from GEMM (incl. b_hh).
__global__ void gru_step_kernel(int j, int n)
{
    int i = blockIdx.x * blockDim.x + threadIdx.x;
    if (i >= n) return;
    int b = i / Hsz, k = i - b * Hsz;
    int idx = d_idx[(j - 1) * Bsz + b];
    const float* gg = d_Gcls + (size_t)b * G3H;
    const float* ap = d_AEp + (size_t)idx * G3H;
    const float* gh = d_gh + (size_t)b * G3H;
    float ir = gg[k] + ap[k];
    float iz = gg[Hsz + k] + ap[Hsz + k];
    float inn = gg[2 * Hsz + k] + ap[2 * Hsz + k];
    float hr = gh[k], hz = gh[Hsz + k], hn = gh[2 * Hsz + k];
    float r = 1.f / (1.f + expf(-(ir + hr)));
    float z = 1.f / (1.f + expf(-(iz + hz)));
    float nn = tanhf(inn + r * hn);
    float hv = (1.f - z) * nn + z * d_h[i];
    d_h[i] = hv;
    float h_, l_; split_hl_f(hv, h_, l_);
    d_a_hi[i] = h_; d_a_lo[i] = l_;
}

// ---------------- selection: gumbel + mask + argmax -----------------------
__global__ __launch_bounds__(256) void select_step_kernel(
    const float* __restrict__ x_, float* __restrict__ out,
    int j, unsigned int sk0, unsigned int sk1)
{
    int b = blockIdx.x;
    int t = threadIdx.x;
    __shared__ float sv[256];
    __shared__ int si[256];
    __shared__ int s_done;

    if (j > 0) {
        if (t == 0) {
            int p = d_idx[(j - 1) * Bsz + b];
            s_done = (p == 0);
            if (p == 0) {
                d_idx[j * Bsz + b] = 0;
                out[((size_t)b * Lsz + j) * Asz + 0] = 1.0f;
            }
        }
        __syncthreads();
        if (s_done) return;
    }

    float best = __int_as_float(0xff800000);
    int bidx = 0x7fffffff;
    const float* lrow = d_logits + (size_t)b * Asz;
    const unsigned int* mrow = d_mask + (size_t)b * (Asz / 32);

    for (int a = t; a < Asz; a += 256) {
        bool valid;
        if (j == 0) valid = (x_[(size_t)b * Asz + a] != 0.0f);
        else        valid = (a == 0) || ((mrow[a >> 5] >> (a & 31)) & 1u);
        if (!valid) continue;

        unsigned long long p = (unsigned long long)b * Asz + (unsigned long long)a;
        unsigned int y0, y1, bits;
#if GUMBEL_PARTITIONABLE
        threefry2x32(sk0, sk1, (unsigned int)(p >> 32), (unsigned int)p, y0, y1);
        bits = y0 ^ y1;
#else
        const unsigned long long NH = (unsigned long long)Bsz * Asz / 2;
        if (p < NH) { threefry2x32(sk0, sk1, (unsigned int)p, (unsigned int)(p + NH), y0, y1); bits = y0; }
        else        { threefry2x32(sk0, sk1, (unsigned int)(p - NH), (unsigned int)p, y0, y1); bits = y1; }
#endif
        float u = __uint_as_float((bits >> 9) | 0x3f800000u) - 1.0f;
        u = fmaxf(u, 1.17549435e-38f);
        float gmb = -logf(-logf(u));
        float v = lrow[a] + gmb;
        if (v > best || (v == best && a < bidx)) { best = v; bidx = a; }
    }

    sv[t] = best; si[t] = bidx;
    __syncthreads();
    for (int s = 128; s > 0; s >>= 1) {
        if (t < s) {
            float v2 = sv[t + s]; int i2 = si[t + s];
            if (v2 > sv[t] || (v2 == sv[t] && i2 < si[t])) { sv[t] = v2; si[t] = i2; }
        }
        __syncthreads();
    }
    if (t == 0) {
        int sel = (si[0] == 0x7fffffff) ? 0 : si[0];
        d_idx[j * Bsz + b] = sel;
        d_mask[(size_t)b * (Asz / 32) + (sel >> 5)] &= ~(1u << (sel & 31));
        out[((size_t)b * Lsz + j) * Asz + sel] = 1.0f;
    }
}

// ======================= launch ===========================================
extern "C" void kernel_launch(void* const* d_in, const int* in_sizes, int n_in,
                              void* d_out, int out_size)
{
    const float* cls    = (const float*)d_in[0];
    const float* x_     = (const float*)d_in[1];
    const float* w_ih   = (const float*)d_in[2];
    const float* w_hh   = (const float*)d_in[3];
    const float* b_ih   = (const float*)d_in[4];
    const float* b_hh   = (const float*)d_in[5];
    const float* head_w = (const float*)d_in[6];
    const float* head_b = (const float*)d_in[7];
    const float* ae_w   = (const float*)d_in[8];
    float* out = (float*)d_out;

    cudaFuncSetAttribute(gemm_tf32x3, cudaFuncAttributeMaxDynamicSharedMemorySize, GEMM_SMEM);

    float *p_wih_hi, *p_wih_lo, *p_whh_hi, *p_whh_lo, *p_hw_hi, *p_hw_lo;
    float *p_a_hi, *p_a_lo, *p_Gcls, *p_AEp, *p_gh, *p_h, *p_logits;
    cudaGetSymbolAddress((void**)&p_wih_hi, d_wih_hi);
    cudaGetSymbolAddress((void**)&p_wih_lo, d_wih_lo);
    cudaGetSymbolAddress((void**)&p_whh_hi, d_whh_hi);
    cudaGetSymbolAddress((void**)&p_whh_lo, d_whh_lo);
    cudaGetSymbolAddress((void**)&p_hw_hi,  d_hw_hi);
    cudaGetSymbolAddress((void**)&p_hw_lo,  d_hw_lo);
    cudaGetSymbolAddress((void**)&p_a_hi,   d_a_hi);
    cudaGetSymbolAddress((void**)&p_a_lo,   d_a_lo);
    cudaGetSymbolAddress((void**)&p_Gcls,   d_Gcls);
    cudaGetSymbolAddress((void**)&p_AEp,    d_AEp);
    cudaGetSymbolAddress((void**)&p_gh,     d_gh);
    cudaGetSymbolAddress((void**)&p_h,      d_h);
    cudaGetSymbolAddress((void**)&p_logits, d_logits);

    // JAX key chain
    unsigned int k0 = 0u, k1 = 42u;
    unsigned int sub[Lsz][2];
    for (int j = 0; j < Lsz; j++) {
#if GUMBEL_PARTITIONABLE
        unsigned int nk0, nk1, s0, s1;
        threefry2x32(k0, k1, 0u, 0u, nk0, nk1);
        threefry2x32(k0, k1, 0u, 1u, s0, s1);
        sub[j][0] = s0; sub[j][1] = s1; k0 = nk0; k1 = nk1;
#else
        unsigned int a0, a1, c0, c1;
        threefry2x32(k0, k1, 0u, 2u, a0, a1);
        threefry2x32(k0, k1, 1u, 3u, c0, c1);
        sub[j][0] = a1; sub[j][1] = c1;
        k0 = a0; k1 = c0;
#endif
    }

    const int BH = Bsz * Hsz;
    const int NW = G3H * Hsz;
    const int NHW = Asz * Hsz;

    zero_out_kernel<<<4096, 256>>>((float4*)out, (size_t)out_size / 4);
    init_mask_kernel<<<(Bsz * Asz / 32 + 255) / 256, 256>>>(x_, Bsz * Asz / 32);

    // weight splits (once)
    split_kernel<<<(NW + 255) / 256, 256>>>(w_ih, p_wih_hi, p_wih_lo, NW);
    split_kernel<<<(NW + 255) / 256, 256>>>(w_hh, p_whh_hi, p_whh_lo, NW);
    split_kernel<<<(NHW + 255) / 256, 256>>>(head_w, p_hw_hi, p_hw_lo, NHW);

    dim3 gGates(G3H / BN, Bsz / BM);   // (18, 32)
    dim3 gHead(Asz / BN, Bsz / BM);    // (32, 32)

    // Precompute: G_cls = cls @ w_ih^T + b_ih
    split_kernel<<<(BH + 255) / 256, 256>>>(cls, p_a_hi, p_a_lo, BH);
    gemm_tf32x3<<<gGates, 256, GEMM_SMEM>>>(p_a_hi, p_a_lo, p_wih_hi, p_wih_lo,
                                            b_ih, p_Gcls, Bsz, G3H, Hsz);
    // Precompute: AE_proj = ae_w @ w_ih^T
    split_kernel<<<(NHW + 255) / 256, 256>>>(ae_w, p_a_hi, p_a_lo, NHW);
    gemm_tf32x3<<<gGates, 256, GEMM_SMEM>>>(p_a_hi, p_a_lo, p_wih_hi, p_wih_lo,
                                            nullptr, p_AEp, Asz, G3H, Hsz);

    // Step 0 (h split written by gru_step0)
    gru_step0_kernel<<<(BH + 255) / 256, 256>>>(b_hh, BH);
    gemm_tf32x3<<<gHead, 256, GEMM_SMEM>>>(p_a_hi, p_a_lo, p_hw_hi, p_hw_lo,
                                           head_b, p_logits, Bsz, Asz, Hsz);
    select_step_kernel<<<Bsz, 256>>>(x_, out, 0, sub[0][0], sub[0][1]);

    for (int j = 1; j < Lsz; j++) {
        gemm_tf32x3<<<gGates, 256, GEMM_SMEM>>>(p_a_hi, p_a_lo, p_whh_hi, p_whh_lo,
                                                b_hh, p_gh, Bsz, G3H, Hsz);
        gru_step_kernel<<<(BH + 255) / 256, 256>>>(j, BH);
        gemm_tf32x3<<<gHead, 256, GEMM_SMEM>>>(p_a_hi, p_a_lo, p_hw_hi, p_hw_lo,
                                               head_b, p_logits, Bsz, Asz, Hsz);
        select_step_kernel<<<Bsz, 256>>>(x_, out, j, sub[j][0], sub[j][1]);
    }
}

// round 9
// speedup vs baseline: 1.2878x; 1.2878x over previous
#include <cuda_runtime.h>
#include <cstdint>
#include <math.h>

#define Bsz 4096
#define Asz 4096
#define Hsz 768
#define Lsz 4
#define G3H (3 * Hsz)   // 2304

#define GUMBEL_PARTITIONABLE 1

// ======================= device scratch ===================================
__device__ float d_Gcls[(size_t)Bsz * G3H];
__device__ float d_AEp[(size_t)Asz * G3H];
__device__ float d_gh[(size_t)Bsz * G3H];
__device__ float d_h[(size_t)Bsz * Hsz];
__device__ float d_logits[(size_t)Bsz * Asz];
__device__ unsigned int d_mask[(size_t)Bsz * Asz / 32];
__device__ int d_idx[Lsz * Bsz];

// ======================= threefry2x32 =====================================
__host__ __device__ __forceinline__ void threefry2x32(
    unsigned int k0, unsigned int k1, unsigned int x0, unsigned int x1,
    unsigned int& o0, unsigned int& o1)
{
    unsigned int ks0 = k0, ks1 = k1, ks2 = k0 ^ k1 ^ 0x1BD11BDAu;
    x0 += ks0; x1 += ks1;
#define TF_RND(r) { x0 += x1; x1 = (x1 << (r)) | (x1 >> (32 - (r))); x1 ^= x0; }
    TF_RND(13) TF_RND(15) TF_RND(26) TF_RND(6)
    x0 += ks1; x1 += ks2 + 1u;
    TF_RND(17) TF_RND(29) TF_RND(16) TF_RND(24)
    x0 += ks2; x1 += ks0 + 2u;
    TF_RND(13) TF_RND(15) TF_RND(26) TF_RND(6)
    x0 += ks0; x1 += ks1 + 3u;
    TF_RND(17) TF_RND(29) TF_RND(16) TF_RND(24)
    x0 += ks1; x1 += ks2 + 4u;
    TF_RND(13) TF_RND(15) TF_RND(26) TF_RND(6)
    x0 += ks2; x1 += ks0 + 5u;
#undef TF_RND
    o0 = x0; o1 = x1;
}

// ======================= tf32x3 mma.sync GEMM =============================
// C[M,N] = A[M,K] @ B[N,K]^T (+bias).  fp32 in; hi = mask-truncated tf32,
// lo = cvt(x - hi) in registers; 3 MMA passes.  Tile 128x128, BK=16,
// 4-stage cp.async pipeline with ONE __syncthreads per chunk.
#define BM 128
#define BN 128
#define BKc 16
#define LDT 20                          // smem row stride in floats
#define NSTG 4
#define ABYTES (BM * LDT * 4)           // 10240
#define BBYTES (BN * LDT * 4)           // 10240
#define GEMM_SMEM (NSTG * (ABYTES + BBYTES))   // 81920

#define CP_ASYNC16(dst_u32, src_ptr) \
    asm volatile("cp.async.cg.shared.global [%0], [%1], 16;" :: "r"(dst_u32), "l"(src_ptr) : "memory")
#define CP_COMMIT() asm volatile("cp.async.commit_group;" ::: "memory")
#define CP_WAIT(n)  asm volatile("cp.async.wait_group %0;" :: "n"(n) : "memory")

__device__ __forceinline__ uint32_t f2tf(float x) {
    uint32_t r; asm("cvt.rna.tf32.f32 %0, %1;" : "=r"(r) : "f"(x));
    return r;
}
__device__ __forceinline__ void split_hl(float x, uint32_t& hi, uint32_t& lo) {
    hi = __float_as_uint(x) & 0xFFFFE000u;
    lo = f2tf(x - __uint_as_float(hi));
}

#define MMA_TF32(c, a, b) \
    asm volatile("mma.sync.aligned.m16n8k8.row.col.f32.tf32.tf32.f32 " \
        "{%0,%1,%2,%3}, {%4,%5,%6,%7}, {%8,%9}, {%0,%1,%2,%3};" \
        : "+f"((c)[0]), "+f"((c)[1]), "+f"((c)[2]), "+f"((c)[3]) \
        : "r"((a)[0]), "r"((a)[1]), "r"((a)[2]), "r"((a)[3]), \
          "r"((b)[0]), "r"((b)[1]))

__device__ __forceinline__ void gemm_core(
    const float* __restrict__ A, const float* __restrict__ Bw,
    const float* __restrict__ bias, float* __restrict__ C,
    int N, int K, int bm, int bn, char* smraw)
{
    const int tid = threadIdx.x;
    const int wid = tid >> 5, lane = tid & 31;
    const int wm = wid >> 1;           // 0..3
    const int wn = wid & 1;            // 0..1
    const int g = lane >> 2;           // 0..7
    const int tg = lane & 3;           // 0..3
    const int NC = K / BKc;            // 48

    uint32_t smb;
    asm("{ .reg .u64 t; cvta.to.shared.u64 t, %1; cvt.u32.u64 %0, t; }"
        : "=r"(smb) : "l"(smraw));

    float acc[2][8][4];
#pragma unroll
    for (int i = 0; i < 2; i++)
#pragma unroll
        for (int j = 0; j < 8; j++)
#pragma unroll
            for (int k = 0; k < 4; k++) acc[i][j][k] = 0.f;

    const int r_ = tid >> 2;            // 0..63
    const int q_ = tid & 3;             // 0..3

    // ---- prologue: load chunks 0,1 into stages 0,1 ----
#pragma unroll
    for (int pc = 0; pc < 2; pc++) {
        const int k0 = pc * BKc;
        const uint32_t sa = smb + pc * ABYTES;
        const uint32_t sb = smb + NSTG * ABYTES + pc * BBYTES;
#pragma unroll
        for (int h = 0; h < 2; h++) {
            int rr = r_ + h * 64;
            CP_ASYNC16(sa + (uint32_t)(rr * LDT + q_ * 4) * 4,
                       A + (size_t)(bm + rr) * K + k0 + q_ * 4);
            CP_ASYNC16(sb + (uint32_t)(rr * LDT + q_ * 4) * 4,
                       Bw + (size_t)(bn + rr) * K + k0 + q_ * 4);
        }
        CP_COMMIT();
    }

    for (int c = 0; c < NC; ++c) {
        if (c + 2 < NC) {
            const int k0 = (c + 2) * BKc;
            const int st = (c + 2) & 3;
            const uint32_t sa = smb + st * ABYTES;
            const uint32_t sb = smb + NSTG * ABYTES + st * BBYTES;
#pragma unroll
            for (int h = 0; h < 2; h++) {
                int rr = r_ + h * 64;
                CP_ASYNC16(sa + (uint32_t)(rr * LDT + q_ * 4) * 4,
                           A + (size_t)(bm + rr) * K + k0 + q_ * 4);
                CP_ASYNC16(sb + (uint32_t)(rr * LDT + q_ * 4) * 4,
                           Bw + (size_t)(bn + rr) * K + k0 + q_ * 4);
            }
            CP_COMMIT();
            CP_WAIT(2);
        } else if (c + 2 == NC) {
            CP_WAIT(1);
        } else {
            CP_WAIT(0);
        }
        __syncthreads();   // single barrier per chunk (4 stages -> no WAR hazard)

        const int st = c & 3;
        const float* SA = (const float*)(smraw + st * ABYTES);
        const float* SB = (const float*)(smraw + NSTG * ABYTES + st * BBYTES);

#pragma unroll
        for (int ks = 0; ks < 2; ks++) {
            const int kk = ks * 8;
            uint32_t ahi[2][4], alo[2][4];
#pragma unroll
            for (int mt = 0; mt < 2; mt++) {
                const int r0 = wm * 32 + mt * 16 + g;
                const int i0 = r0 * LDT + kk + tg;
                float x0 = SA[i0];
                float x1 = SA[i0 + 8 * LDT];
                float x2 = SA[i0 + 4];
                float x3 = SA[i0 + 8 * LDT + 4];
                split_hl(x0, ahi[mt][0], alo[mt][0]);
                split_hl(x1, ahi[mt][1], alo[mt][1]);
                split_hl(x2, ahi[mt][2], alo[mt][2]);
                split_hl(x3, ahi[mt][3], alo[mt][3]);
            }
#pragma unroll
            for (int hb = 0; hb < 2; hb++) {
                uint32_t bhi[4][2], blo[4][2];
#pragma unroll
                for (int nt = 0; nt < 4; nt++) {
                    const int n0 = wn * 64 + (hb * 4 + nt) * 8 + g;
                    const int i0 = n0 * LDT + kk + tg;
                    float y0 = SB[i0];
                    float y1 = SB[i0 + 4];
                    split_hl(y0, bhi[nt][0], blo[nt][0]);
                    split_hl(y1, bhi[nt][1], blo[nt][1]);
                }
#pragma unroll
                for (int mt = 0; mt < 2; mt++)
#pragma unroll
                    for (int nt = 0; nt < 4; nt++)
                        MMA_TF32(acc[mt][hb * 4 + nt], ahi[mt], blo[nt]);
#pragma unroll
                for (int mt = 0; mt < 2; mt++)
#pragma unroll
                    for (int nt = 0; nt < 4; nt++)
                        MMA_TF32(acc[mt][hb * 4 + nt], alo[mt], bhi[nt]);
#pragma unroll
                for (int mt = 0; mt < 2; mt++)
#pragma unroll
                    for (int nt = 0; nt < 4; nt++)
                        MMA_TF32(acc[mt][hb * 4 + nt], ahi[mt], bhi[nt]);
            }
        }
    }

    // ---- epilogue ----
#pragma unroll
    for (int mt = 0; mt < 2; mt++) {
        const int r0 = bm + wm * 32 + mt * 16 + g;
#pragma unroll
        for (int nt = 0; nt < 8; nt++) {
            const int n0 = bn + wn * 64 + nt * 8 + tg * 2;
            float bx = 0.f, by = 0.f;
            if (bias) { bx = bias[n0]; by = bias[n0 + 1]; }
            float2 v0 = make_float2(acc[mt][nt][0] + bx, acc[mt][nt][1] + by);
            float2 v1 = make_float2(acc[mt][nt][2] + bx, acc[mt][nt][3] + by);
            *(float2*)(C + (size_t)r0 * N + n0) = v0;
            *(float2*)(C + (size_t)(r0 + 8) * N + n0) = v1;
        }
    }
}

__global__ void __launch_bounds__(256, 2)
gemm_tf32x3(const float* __restrict__ A, const float* __restrict__ Bw,
            const float* __restrict__ bias, float* __restrict__ C,
            int N, int K)
{
    extern __shared__ char smraw[];
    gemm_core(A, Bw, bias, C, N, K, blockIdx.y * BM, blockIdx.x * BN, smraw);
}

// Dual-output GEMM: one A, two weight/bias/output sets (gh + logits).
__global__ void __launch_bounds__(256, 2)
gemm_tf32x3_dual(const float* __restrict__ A,
                 const float* __restrict__ B1, const float* __restrict__ bias1,
                 float* __restrict__ C1, int N1,
                 const float* __restrict__ B2, const float* __restrict__ bias2,
                 float* __restrict__ C2, int N2,
                 int K, int xsplit)
{
    extern __shared__ char smraw[];
    const int bx = blockIdx.x;
    if (bx < xsplit)
        gemm_core(A, B1, bias1, C1, N1, K, blockIdx.y * BM, bx * BN, smraw);
    else
        gemm_core(A, B2, bias2, C2, N2, K, blockIdx.y * BM, (bx - xsplit) * BN, smraw);
}

// ======================= elementwise kernels ==============================
__global__ void init_mask_kernel(const float* __restrict__ x_, int nwords)
{
    int w = blockIdx.x * blockDim.x + threadIdx.x;
    if (w >= nwords) return;
    int b = w >> 7;
    int wa = w & 127;
    const float* xr = x_ + (size_t)b * Asz + wa * 32;
    unsigned int bits = 0;
#pragma unroll
    for (int e = 0; e < 32; e++)
        if (xr[e] != 0.0f) bits |= (1u << e);
    d_mask[w] = bits;
}

// Step 0: h_prev = 0 -> gh = b_hh exactly; h = (1-z)*n.
__global__ void gru_step0_kernel(const float* __restrict__ b_hh, int n)
{
    int i = blockIdx.x * blockDim.x + threadIdx.x;
    if (i >= n) return;
    int b = i / Hsz, k = i - b * Hsz;
    const float* gg = d_Gcls + (size_t)b * G3H;
    float ir = gg[k], iz = gg[Hsz + k], inn = gg[2 * Hsz + k];
    float hr = b_hh[k], hz = b_hh[Hsz + k], hn = b_hh[2 * Hsz + k];
    float r = 1.f / (1.f + expf(-(ir + hr)));
    float z = 1.f / (1.f + expf(-(iz + hz)));
    float nn = tanhf(inn + r * hn);
    d_h[i] = (1.f - z) * nn;
}

// Step j>=1: gi = G_cls + AE_proj[idx_{j-1}]; gh from GEMM (incl. b_hh).
__global__ void gru_step_kernel(int j, int n)
{
    int i = blockIdx.x * blockDim.x + threadIdx.x;
    if (i >= n) return;
    int b = i / Hsz, k = i - b * Hsz;
    int idx = d_idx[(j - 1) * Bsz + b];
    const float* gg = d_Gcls + (size_t)b * G3H;
    const float* ap = d_AEp + (size_t)idx * G3H;
    const float* gh = d_gh + (size_t)b * G3H;
    float ir = gg[k] + ap[k];
    float iz = gg[Hsz + k] + ap[Hsz + k];
    float inn = gg[2 * Hsz + k] + ap[2 * Hsz + k];
    float hr = gh[k], hz = gh[Hsz + k], hn = gh[2 * Hsz + k];
    float r = 1.f / (1.f + expf(-(ir + hr)));
    float z = 1.f / (1.f + expf(-(iz + hz)));
    float nn = tanhf(inn + r * hn);
    d_h[i] = (1.f - z) * nn + z * d_h[i];
}

// ---------------- selection: gumbel + mask + argmax; writes FULL row ------
__global__ __launch_bounds__(256) void select_step_kernel(
    const float* __restrict__ x_, float* __restrict__ out,
    int j, unsigned int sk0, unsigned int sk1)
{
    int b = blockIdx.x;
    int t = threadIdx.x;
    __shared__ float sv[256];
    __shared__ int si[256];
    __shared__ int s_done;
    __shared__ int s_sel;

    bool done = false;
    if (j > 0) {
        if (t == 0) s_done = (d_idx[(j - 1) * Bsz + b] == 0);
        __syncthreads();
        done = (s_done != 0);
    }

    if (!done) {
        float best = __int_as_float(0xff800000);
        int bidx = 0x7fffffff;
        const float* lrow = d_logits + (size_t)b * Asz;
        const unsigned int* mrow = d_mask + (size_t)b * (Asz / 32);

        for (int a = t; a < Asz; a += 256) {
            bool valid;
            if (j == 0) valid = (x_[(size_t)b * Asz + a] != 0.0f);
            else        valid = (a == 0) || ((mrow[a >> 5] >> (a & 31)) & 1u);
            if (!valid) continue;

            unsigned long long p = (unsigned long long)b * Asz + (unsigned long long)a;
            unsigned int y0, y1, bits;
#if GUMBEL_PARTITIONABLE
            threefry2x32(sk0, sk1, (unsigned int)(p >> 32), (unsigned int)p, y0, y1);
            bits = y0 ^ y1;
#else
            const unsigned long long NH = (unsigned long long)Bsz * Asz / 2;
            if (p < NH) { threefry2x32(sk0, sk1, (unsigned int)p, (unsigned int)(p + NH), y0, y1); bits = y0; }
            else        { threefry2x32(sk0, sk1, (unsigned int)(p - NH), (unsigned int)p, y0, y1); bits = y1; }
#endif
            float u = __uint_as_float((bits >> 9) | 0x3f800000u) - 1.0f;
            u = fmaxf(u, 1.17549435e-38f);
            float gmb = -logf(-logf(u));
            float v = lrow[a] + gmb;
            if (v > best || (v == best && a < bidx)) { best = v; bidx = a; }
        }

        sv[t] = best; si[t] = bidx;
        __syncthreads();
        for (int s = 128; s > 0; s >>= 1) {
            if (t < s) {
                float v2 = sv[t + s]; int i2 = si[t + s];
                if (v2 > sv[t] || (v2 == sv[t] && i2 < si[t])) { sv[t] = v2; si[t] = i2; }
            }
            __syncthreads();
        }
        if (t == 0) s_sel = (si[0] == 0x7fffffff) ? 0 : si[0];
    } else {
        if (t == 0) s_sel = 0;
    }
    __syncthreads();
    const int sel = s_sel;

    // write the full one-hot row (out is poisoned, must initialize)
    float4* orow4 = (float4*)(out + ((size_t)b * Lsz + j) * Asz);
    float4 z4 = make_float4(0.f, 0.f, 0.f, 0.f);
    for (int a4 = t; a4 < Asz / 4; a4 += 256) orow4[a4] = z4;
    __syncthreads();
    if (t == 0) {
        ((float*)orow4)[sel] = 1.0f;
        d_idx[j * Bsz + b] = sel;
        d_mask[(size_t)b * (Asz / 32) + (sel >> 5)] &= ~(1u << (sel & 31));
    }
}

// ======================= launch ===========================================
extern "C" void kernel_launch(void* const* d_in, const int* in_sizes, int n_in,
                              void* d_out, int out_size)
{
    const float* cls    = (const float*)d_in[0];
    const float* x_     = (const float*)d_in[1];
    const float* w_ih   = (const float*)d_in[2];
    const float* w_hh   = (const float*)d_in[3];
    const float* b_ih   = (const float*)d_in[4];
    const float* b_hh   = (const float*)d_in[5];
    const float* head_w = (const float*)d_in[6];
    const float* head_b = (const float*)d_in[7];
    const float* ae_w   = (const float*)d_in[8];
    float* out = (float*)d_out;

    cudaFuncSetAttribute(gemm_tf32x3, cudaFuncAttributeMaxDynamicSharedMemorySize, GEMM_SMEM);
    cudaFuncSetAttribute(gemm_tf32x3_dual, cudaFuncAttributeMaxDynamicSharedMemorySize, GEMM_SMEM);

    float *p_Gcls, *p_AEp, *p_gh, *p_h, *p_logits;
    cudaGetSymbolAddress((void**)&p_Gcls,   d_Gcls);
    cudaGetSymbolAddress((void**)&p_AEp,    d_AEp);
    cudaGetSymbolAddress((void**)&p_gh,     d_gh);
    cudaGetSymbolAddress((void**)&p_h,      d_h);
    cudaGetSymbolAddress((void**)&p_logits, d_logits);

    // JAX key chain
    unsigned int k0 = 0u, k1 = 42u;
    unsigned int sub[Lsz][2];
    for (int j = 0; j < Lsz; j++) {
#if GUMBEL_PARTITIONABLE
        unsigned int nk0, nk1, s0, s1;
        threefry2x32(k0, k1, 0u, 0u, nk0, nk1);
        threefry2x32(k0, k1, 0u, 1u, s0, s1);
        sub[j][0] = s0; sub[j][1] = s1; k0 = nk0; k1 = nk1;
#else
        unsigned int a0, a1, c0, c1;
        threefry2x32(k0, k1, 0u, 2u, a0, a1);
        threefry2x32(k0, k1, 1u, 3u, c0, c1);
        sub[j][0] = a1; sub[j][1] = c1;
        k0 = a0; k1 = c0;
#endif
    }

    const int BH = Bsz * Hsz;

    init_mask_kernel<<<(Bsz * Asz / 32 + 255) / 256, 256>>>(x_, Bsz * Asz / 32);

    dim3 gGates(G3H / BN, Bsz / BM);            // (18, 32)
    dim3 gHead(Asz / BN, Bsz / BM);             // (32, 32)
    dim3 gDual(G3H / BN + Asz / BN, Bsz / BM);  // (50, 32)
    const int xsplit = G3H / BN;                // 18

    // Precompute: G_cls = cls @ w_ih^T + b_ih ; AE_proj = ae_w @ w_ih^T
    gemm_tf32x3<<<gGates, 256, GEMM_SMEM>>>(cls,  w_ih, b_ih,    p_Gcls, G3H, Hsz);
    gemm_tf32x3<<<gGates, 256, GEMM_SMEM>>>(ae_w, w_ih, nullptr, p_AEp,  G3H, Hsz);

    // Step 0
    gru_step0_kernel<<<(BH + 255) / 256, 256>>>(b_hh, BH);

    for (int j = 0; j < Lsz; j++) {
        if (j < Lsz - 1) {
            // gh_{j+1} = h_j @ w_hh^T + b_hh  AND  logits_j = h_j @ head_w^T + head_b
            gemm_tf32x3_dual<<<gDual, 256, GEMM_SMEM>>>(
                p_h, w_hh, b_hh, p_gh, G3H,
                head_w, head_b, p_logits, Asz, Hsz, xsplit);
        } else {
            gemm_tf32x3<<<gHead, 256, GEMM_SMEM>>>(p_h, head_w, head_b,
                                                   p_logits, Asz, Hsz);
        }
        select_step_kernel<<<Bsz, 256>>>(x_, out, j, sub[j][0], sub[j][1]);
        if (j < Lsz - 1)
            gru_step_kernel<<<(BH + 255) / 256, 256>>>(j + 1, BH);
    }
}

// round 10
// speedup vs baseline: 1.7554x; 1.3631x over previous
#include <cuda_runtime.h>
#include <cuda_fp16.h>
#include <cstdint>
#include <math.h>

#define Bsz 4096
#define Asz 4096
#define Hsz 768
#define Lsz 4
#define G3H (3 * Hsz)   // 2304

#define GUMBEL_PARTITIONABLE 1

// ======================= device scratch ===================================
__device__ __half d_wih_hi[(size_t)G3H * Hsz];
__device__ __half d_wih_lo[(size_t)G3H * Hsz];
__device__ __half d_whh_hi[(size_t)G3H * Hsz];
__device__ __half d_whh_lo[(size_t)G3H * Hsz];
__device__ __half d_hw_hi[(size_t)Asz * Hsz];
__device__ __half d_hw_lo[(size_t)Asz * Hsz];
__device__ __half d_a_hi[(size_t)Asz * Hsz];   // A-side split (cls / ae_w / h)
__device__ __half d_a_lo[(size_t)Asz * Hsz];
__device__ float d_Gcls[(size_t)Bsz * G3H];
__device__ float d_AEp[(size_t)Asz * G3H];
__device__ float d_gh[(size_t)Bsz * G3H];
__device__ float d_h[(size_t)Bsz * Hsz];
__device__ float d_logits[(size_t)Bsz * Asz];
__device__ unsigned int d_mask[(size_t)Bsz * Asz / 32];
__device__ int d_idx[Lsz * Bsz];

// ======================= threefry2x32 =====================================
__host__ __device__ __forceinline__ void threefry2x32(
    unsigned int k0, unsigned int k1, unsigned int x0, unsigned int x1,
    unsigned int& o0, unsigned int& o1)
{
    unsigned int ks0 = k0, ks1 = k1, ks2 = k0 ^ k1 ^ 0x1BD11BDAu;
    x0 += ks0; x1 += ks1;
#define TF_RND(r) { x0 += x1; x1 = (x1 << (r)) | (x1 >> (32 - (r))); x1 ^= x0; }
    TF_RND(13) TF_RND(15) TF_RND(26) TF_RND(6)
    x0 += ks1; x1 += ks2 + 1u;
    TF_RND(17) TF_RND(29) TF_RND(16) TF_RND(24)
    x0 += ks2; x1 += ks0 + 2u;
    TF_RND(13) TF_RND(15) TF_RND(26) TF_RND(6)
    x0 += ks0; x1 += ks1 + 3u;
    TF_RND(17) TF_RND(29) TF_RND(16) TF_RND(24)
    x0 += ks1; x1 += ks2 + 4u;
    TF_RND(13) TF_RND(15) TF_RND(26) TF_RND(6)
    x0 += ks2; x1 += ks0 + 5u;
#undef TF_RND
    o0 = x0; o1 = x1;
}

// ======================= fp16 hi/lo split =================================
__device__ __forceinline__ void split_f16(float x, __half& hi, __half& lo)
{
    __half h = __float2half_rn(x);
    float hf = __half2float(h);
    hi = h;
    lo = __float2half_rn(x - hf);   // may be denormal; HMMA handles exactly
}

// ======================= fp16x2 mma.sync GEMM =============================
// C[M,N] = A[M,K] @ B[N,K]^T (+bias).  A/B pre-split into fp16 hi/lo arrays
// (row-major [rows][K], k contiguous -> fp16x2 words).  3 products per k16:
// ah*bl + al*bh + ah*bh, all into one fp32 accumulator.
// Tile 128x128, k-chunk 16, 4-stage cp.async pipeline, one barrier/chunk.
#define BM 128
#define BN 128
#define BKc 16
#define NSTG 4
#define LDW 12                          // smem row stride in 32-bit words (8 data + 4 pad)
#define AST (128 * LDW * 4)             // 6144 B per array per stage
#define STG_BYTES (4 * AST)             // 24576 B (Ahi, Alo, Bhi, Blo)
#define GEMM_SMEM (NSTG * STG_BYTES)    // 98304 B

#define CP_ASYNC16(dst_u32, src_ptr) \
    asm volatile("cp.async.cg.shared.global [%0], [%1], 16;" :: "r"(dst_u32), "l"(src_ptr) : "memory")
#define CP_COMMIT() asm volatile("cp.async.commit_group;" ::: "memory")
#define CP_WAIT(n)  asm volatile("cp.async.wait_group %0;" :: "n"(n) : "memory")

#define MMA_F16(c, a, b) \
    asm volatile("mma.sync.aligned.m16n8k16.row.col.f32.f16.f16.f32 " \
        "{%0,%1,%2,%3}, {%4,%5,%6,%7}, {%8,%9}, {%0,%1,%2,%3};" \
        : "+f"((c)[0]), "+f"((c)[1]), "+f"((c)[2]), "+f"((c)[3]) \
        : "r"((a)[0]), "r"((a)[1]), "r"((a)[2]), "r"((a)[3]), \
          "r"((b)[0]), "r"((b)[1]))

__device__ __forceinline__ void gemm_core(
    const __half* __restrict__ Ahi, const __half* __restrict__ Alo,
    const __half* __restrict__ Bhi, const __half* __restrict__ Blo,
    const float* __restrict__ bias, float* __restrict__ C,
    int N, int K, int bm, int bn, char* smraw)
{
    const int tid = threadIdx.x;
    const int wid = tid >> 5, lane = tid & 31;
    const int wm = wid >> 1;           // 0..3
    const int wn = wid & 1;            // 0..1
    const int g = lane >> 2;           // 0..7
    const int tg = lane & 3;           // 0..3
    const int NC = K / BKc;            // 48

    uint32_t smb;
    asm("{ .reg .u64 t; cvta.to.shared.u64 t, %1; cvt.u32.u64 %0, t; }"
        : "=r"(smb) : "l"(smraw));

    float acc[2][8][4];
#pragma unroll
    for (int i = 0; i < 2; i++)
#pragma unroll
        for (int j = 0; j < 8; j++)
#pragma unroll
            for (int k = 0; k < 4; k++) acc[i][j][k] = 0.f;

    // cp.async coords: 256 threads cover 128 rows x 2 16B-pieces per array
    const int rr = tid >> 1;            // 0..127
    const int qq = tid & 1;             // 0..1 (which 16B half-row = 8 halves)

    // ---- prologue: chunks 0,1 -> stages 0,1 ----
#pragma unroll
    for (int pc = 0; pc < 2; pc++) {
        const int k0 = pc * BKc;
        const uint32_t sbase = smb + pc * STG_BYTES + (uint32_t)(rr * (LDW * 4) + qq * 16);
        const size_t ga = (size_t)(bm + rr) * K + k0 + qq * 8;
        const size_t gb = (size_t)(bn + rr) * K + k0 + qq * 8;
        CP_ASYNC16(sbase,           Ahi + ga);
        CP_ASYNC16(sbase + AST,     Alo + ga);
        CP_ASYNC16(sbase + 2 * AST, Bhi + gb);
        CP_ASYNC16(sbase + 3 * AST, Blo + gb);
        CP_COMMIT();
    }

    for (int c = 0; c < NC; ++c) {
        if (c + 2 < NC) {
            const int k0 = (c + 2) * BKc;
            const int st = (c + 2) & 3;
            const uint32_t sbase = smb + st * STG_BYTES + (uint32_t)(rr * (LDW * 4) + qq * 16);
            const size_t ga = (size_t)(bm + rr) * K + k0 + qq * 8;
            const size_t gb = (size_t)(bn + rr) * K + k0 + qq * 8;
            CP_ASYNC16(sbase,           Ahi + ga);
            CP_ASYNC16(sbase + AST,     Alo + ga);
            CP_ASYNC16(sbase + 2 * AST, Bhi + gb);
            CP_ASYNC16(sbase + 3 * AST, Blo + gb);
            CP_COMMIT();
            CP_WAIT(2);
        } else if (c + 2 == NC) {
            CP_WAIT(1);
        } else {
            CP_WAIT(0);
        }
        __syncthreads();   // single barrier per chunk (4 stages, no WAR hazard)

        const int st = c & 3;
        const uint32_t* SAh = (const uint32_t*)(smraw + st * STG_BYTES);
        const uint32_t* SAl = (const uint32_t*)(smraw + st * STG_BYTES + AST);
        const uint32_t* SBh = (const uint32_t*)(smraw + st * STG_BYTES + 2 * AST);
        const uint32_t* SBl = (const uint32_t*)(smraw + st * STG_BYTES + 3 * AST);

        uint32_t ahi[2][4], alo[2][4];
#pragma unroll
        for (int mt = 0; mt < 2; mt++) {
            const int r0 = wm * 32 + mt * 16 + g;
            const int i0 = r0 * LDW + tg;
            ahi[mt][0] = SAh[i0];
            ahi[mt][1] = SAh[i0 + 8 * LDW];
            ahi[mt][2] = SAh[i0 + 4];
            ahi[mt][3] = SAh[i0 + 8 * LDW + 4];
            alo[mt][0] = SAl[i0];
            alo[mt][1] = SAl[i0 + 8 * LDW];
            alo[mt][2] = SAl[i0 + 4];
            alo[mt][3] = SAl[i0 + 8 * LDW + 4];
        }
#pragma unroll
        for (int hb = 0; hb < 2; hb++) {
            uint32_t bhi[4][2], blo[4][2];
#pragma unroll
            for (int nt = 0; nt < 4; nt++) {
                const int n0 = wn * 64 + (hb * 4 + nt) * 8 + g;
                const int i0 = n0 * LDW + tg;
                bhi[nt][0] = SBh[i0];
                bhi[nt][1] = SBh[i0 + 4];
                blo[nt][0] = SBl[i0];
                blo[nt][1] = SBl[i0 + 4];
            }
            // 3 passes of 8 independent MMAs (dep distance 8)
#pragma unroll
            for (int mt = 0; mt < 2; mt++)
#pragma unroll
                for (int nt = 0; nt < 4; nt++)
                    MMA_F16(acc[mt][hb * 4 + nt], ahi[mt], blo[nt]);
#pragma unroll
            for (int mt = 0; mt < 2; mt++)
#pragma unroll
                for (int nt = 0; nt < 4; nt++)
                    MMA_F16(acc[mt][hb * 4 + nt], alo[mt], bhi[nt]);
#pragma unroll
            for (int mt = 0; mt < 2; mt++)
#pragma unroll
                for (int nt = 0; nt < 4; nt++)
                    MMA_F16(acc[mt][hb * 4 + nt], ahi[mt], bhi[nt]);
        }
    }

    // ---- epilogue ----
#pragma unroll
    for (int mt = 0; mt < 2; mt++) {
        const int r0 = bm + wm * 32 + mt * 16 + g;
#pragma unroll
        for (int nt = 0; nt < 8; nt++) {
            const int n0 = bn + wn * 64 + nt * 8 + tg * 2;
            float bx = 0.f, by = 0.f;
            if (bias) { bx = bias[n0]; by = bias[n0 + 1]; }
            float2 v0 = make_float2(acc[mt][nt][0] + bx, acc[mt][nt][1] + by);
            float2 v1 = make_float2(acc[mt][nt][2] + bx, acc[mt][nt][3] + by);
            *(float2*)(C + (size_t)r0 * N + n0) = v0;
            *(float2*)(C + (size_t)(r0 + 8) * N + n0) = v1;
        }
    }
}

__global__ void __launch_bounds__(256, 2)
gemm_f16x2(const __half* __restrict__ Ahi, const __half* __restrict__ Alo,
           const __half* __restrict__ Bhi, const __half* __restrict__ Blo,
           const float* __restrict__ bias, float* __restrict__ C,
           int N, int K)
{
    extern __shared__ char smraw[];
    gemm_core(Ahi, Alo, Bhi, Blo, bias, C, N, K,
              blockIdx.y * BM, blockIdx.x * BN, smraw);
}

// Dual-output GEMM: one A, two weight/bias/output sets (gh + logits).
__global__ void __launch_bounds__(256, 2)
gemm_f16x2_dual(const __half* __restrict__ Ahi, const __half* __restrict__ Alo,
                const __half* __restrict__ B1h, const __half* __restrict__ B1l,
                const float* __restrict__ bias1, float* __restrict__ C1, int N1,
                const __half* __restrict__ B2h, const __half* __restrict__ B2l,
                const float* __restrict__ bias2, float* __restrict__ C2, int N2,
                int K, int xsplit)
{
    extern __shared__ char smraw[];
    const int bx = blockIdx.x;
    if (bx < xsplit)
        gemm_core(Ahi, Alo, B1h, B1l, bias1, C1, N1, K,
                  blockIdx.y * BM, bx * BN, smraw);
    else
        gemm_core(Ahi, Alo, B2h, B2l, bias2, C2, N2, K,
                  blockIdx.y * BM, (bx - xsplit) * BN, smraw);
}

// ======================= elementwise kernels ==============================
__global__ void split_kernel(const float* __restrict__ src,
                             __half* __restrict__ hi, __half* __restrict__ lo, int n)
{
    int i = blockIdx.x * blockDim.x + threadIdx.x;
    if (i >= n) return;
    __half h, l; split_f16(src[i], h, l);
    hi[i] = h; lo[i] = l;
}

__global__ void init_mask_kernel(const float* __restrict__ x_, int nwords)
{
    int w = blockIdx.x * blockDim.x + threadIdx.x;
    if (w >= nwords) return;
    int b = w >> 7;
    int wa = w & 127;
    const float* xr = x_ + (size_t)b * Asz + wa * 32;
    unsigned int bits = 0;
#pragma unroll
    for (int e = 0; e < 32; e++)
        if (xr[e] != 0.0f) bits |= (1u << e);
    d_mask[w] = bits;
}

// Step 0: h_prev = 0 -> gh = b_hh exactly; h = (1-z)*n.  Writes h + fp16 split.
__global__ void gru_step0_kernel(const float* __restrict__ b_hh, int n)
{
    int i = blockIdx.x * blockDim.x + threadIdx.x;
    if (i >= n) return;
    int b = i / Hsz, k = i - b * Hsz;
    const float* gg = d_Gcls + (size_t)b * G3H;
    float ir = gg[k], iz = gg[Hsz + k], inn = gg[2 * Hsz + k];
    float hr = b_hh[k], hz = b_hh[Hsz + k], hn = b_hh[2 * Hsz + k];
    float r = 1.f / (1.f + expf(-(ir + hr)));
    float z = 1.f / (1.f + expf(-(iz + hz)));
    float nn = tanhf(inn + r * hn);
    float hv = (1.f - z) * nn;
    d_h[i] = hv;
    __half h_, l_; split_f16(hv, h_, l_);
    d_a_hi[i] = h_; d_a_lo[i] = l_;
}

// Step j>=1: gi = G_cls + AE_proj[idx_{j-1}]; gh from GEMM (incl. b_hh).
__global__ void gru_step_kernel(int j, int n)
{
    int i = blockIdx.x * blockDim.x + threadIdx.x;
    if (i >= n) return;
    int b = i / Hsz, k = i - b * Hsz;
    int idx = d_idx[(j - 1) * Bsz + b];
    const float* gg = d_Gcls + (size_t)b * G3H;
    const float* ap = d_AEp + (size_t)idx * G3H;
    const float* gh = d_gh + (size_t)b * G3H;
    float ir = gg[k] + ap[k];
    float iz = gg[Hsz + k] + ap[Hsz + k];
    float inn = gg[2 * Hsz + k] + ap[2 * Hsz + k];
    float hr = gh[k], hz = gh[Hsz + k], hn = gh[2 * Hsz + k];
    float r = 1.f / (1.f + expf(-(ir + hr)));
    float z = 1.f / (1.f + expf(-(iz + hz)));
    float nn = tanhf(inn + r * hn);
    float hv = (1.f - z) * nn + z * d_h[i];
    d_h[i] = hv;
    __half h_, l_; split_f16(hv, h_, l_);
    d_a_hi[i] = h_; d_a_lo[i] = l_;
}

// ---------------- selection: gumbel + mask + argmax; writes FULL row ------
__global__ __launch_bounds__(256) void select_step_kernel(
    const float* __restrict__ x_, float* __restrict__ out,
    int j, unsigned int sk0, unsigned int sk1)
{
    int b = blockIdx.x;
    int t = threadIdx.x;
    __shared__ float sv[256];
    __shared__ int si[256];
    __shared__ int s_done;
    __shared__ int s_sel;

    bool done = false;
    if (j > 0) {
        if (t == 0) s_done = (d_idx[(j - 1) * Bsz + b] == 0);
        __syncthreads();
        done = (s_done != 0);
    }

    if (!done) {
        float best = __int_as_float(0xff800000);
        int bidx = 0x7fffffff;
        const float* lrow = d_logits + (size_t)b * Asz;
        const unsigned int* mrow = d_mask + (size_t)b * (Asz / 32);

        for (int a = t; a < Asz; a += 256) {
            bool valid;
            if (j == 0) valid = (x_[(size_t)b * Asz + a] != 0.0f);
            else        valid = (a == 0) || ((mrow[a >> 5] >> (a & 31)) & 1u);
            if (!valid) continue;

            unsigned long long p = (unsigned long long)b * Asz + (unsigned long long)a;
            unsigned int y0, y1, bits;
#if GUMBEL_PARTITIONABLE
            threefry2x32(sk0, sk1, (unsigned int)(p >> 32), (unsigned int)p, y0, y1);
            bits = y0 ^ y1;
#else
            const unsigned long long NH = (unsigned long long)Bsz * Asz / 2;
            if (p < NH) { threefry2x32(sk0, sk1, (unsigned int)p, (unsigned int)(p + NH), y0, y1); bits = y0; }
            else        { threefry2x32(sk0, sk1, (unsigned int)(p - NH), (unsigned int)p, y0, y1); bits = y1; }
#endif
            float u = __uint_as_float((bits >> 9) | 0x3f800000u) - 1.0f;
            u = fmaxf(u, 1.17549435e-38f);
            float gmb = -logf(-logf(u));
            float v = lrow[a] + gmb;
            if (v > best || (v == best && a < bidx)) { best = v; bidx = a; }
        }

        sv[t] = best; si[t] = bidx;
        __syncthreads();
        for (int s = 128; s > 0; s >>= 1) {
            if (t < s) {
                float v2 = sv[t + s]; int i2 = si[t + s];
                if (v2 > sv[t] || (v2 == sv[t] && i2 < si[t])) { sv[t] = v2; si[t] = i2; }
            }
            __syncthreads();
        }
        if (t == 0) s_sel = (si[0] == 0x7fffffff) ? 0 : si[0];
    } else {
        if (t == 0) s_sel = 0;
    }
    __syncthreads();
    const int sel = s_sel;

    // write the full one-hot row (out is poisoned, must initialize)
    float4* orow4 = (float4*)(out + ((size_t)b * Lsz + j) * Asz);
    float4 z4 = make_float4(0.f, 0.f, 0.f, 0.f);
    for (int a4 = t; a4 < Asz / 4; a4 += 256) orow4[a4] = z4;
    __syncthreads();
    if (t == 0) {
        ((float*)orow4)[sel] = 1.0f;
        d_idx[j * Bsz + b] = sel;
        d_mask[(size_t)b * (Asz / 32) + (sel >> 5)] &= ~(1u << (sel & 31));
    }
}

// ======================= launch ===========================================
extern "C" void kernel_launch(void* const* d_in, const int* in_sizes, int n_in,
                              void* d_out, int out_size)
{
    const float* cls    = (const float*)d_in[0];
    const float* x_     = (const float*)d_in[1];
    const float* w_ih   = (const float*)d_in[2];
    const float* w_hh   = (const float*)d_in[3];
    const float* b_ih   = (const float*)d_in[4];
    const float* b_hh   = (const float*)d_in[5];
    const float* head_w = (const float*)d_in[6];
    const float* head_b = (const float*)d_in[7];
    const float* ae_w   = (const float*)d_in[8];
    float* out = (float*)d_out;

    cudaFuncSetAttribute(gemm_f16x2, cudaFuncAttributeMaxDynamicSharedMemorySize, GEMM_SMEM);
    cudaFuncSetAttribute(gemm_f16x2_dual, cudaFuncAttributeMaxDynamicSharedMemorySize, GEMM_SMEM);

    __half *p_wih_hi, *p_wih_lo, *p_whh_hi, *p_whh_lo, *p_hw_hi, *p_hw_lo, *p_a_hi, *p_a_lo;
    float *p_Gcls, *p_AEp, *p_gh, *p_h, *p_logits;
    cudaGetSymbolAddress((void**)&p_wih_hi, d_wih_hi);
    cudaGetSymbolAddress((void**)&p_wih_lo, d_wih_lo);
    cudaGetSymbolAddress((void**)&p_whh_hi, d_whh_hi);
    cudaGetSymbolAddress((void**)&p_whh_lo, d_whh_lo);
    cudaGetSymbolAddress((void**)&p_hw_hi,  d_hw_hi);
    cudaGetSymbolAddress((void**)&p_hw_lo,  d_hw_lo);
    cudaGetSymbolAddress((void**)&p_a_hi,   d_a_hi);
    cudaGetSymbolAddress((void**)&p_a_lo,   d_a_lo);
    cudaGetSymbolAddress((void**)&p_Gcls,   d_Gcls);
    cudaGetSymbolAddress((void**)&p_AEp,    d_AEp);
    cudaGetSymbolAddress((void**)&p_gh,     d_gh);
    cudaGetSymbolAddress((void**)&p_h,      d_h);
    cudaGetSymbolAddress((void**)&p_logits, d_logits);

    // JAX key chain
    unsigned int k0 = 0u, k1 = 42u;
    unsigned int sub[Lsz][2];
    for (int j = 0; j < Lsz; j++) {
#if GUMBEL_PARTITIONABLE
        unsigned int nk0, nk1, s0, s1;
        threefry2x32(k0, k1, 0u, 0u, nk0, nk1);
        threefry2x32(k0, k1, 0u, 1u, s0, s1);
        sub[j][0] = s0; sub[j][1] = s1; k0 = nk0; k1 = nk1;
#else
        unsigned int a0, a1, c0, c1;
        threefry2x32(k0, k1, 0u, 2u, a0, a1);
        threefry2x32(k0, k1, 1u, 3u, c0, c1);
        sub[j][0] = a1; sub[j][1] = c1;
        k0 = a0; k1 = c0;
#endif
    }

    const int BH = Bsz * Hsz;
    const int NW = G3H * Hsz;
    const int NHW = Asz * Hsz;

    init_mask_kernel<<<(Bsz * Asz / 32 + 255) / 256, 256>>>(x_, Bsz * Asz / 32);

    // weight splits (once)
    split_kernel<<<(NW + 255) / 256, 256>>>(w_ih, p_wih_hi, p_wih_lo, NW);
    split_kernel<<<(NW + 255) / 256, 256>>>(w_hh, p_whh_hi, p_whh_lo, NW);
    split_kernel<<<(NHW + 255) / 256, 256>>>(head_w, p_hw_hi, p_hw_lo, NHW);

    dim3 gGates(G3H / BN, Bsz / BM);            // (18, 32)
    dim3 gHead(Asz / BN, Bsz / BM);             // (32, 32)
    dim3 gDual(G3H / BN + Asz / BN, Bsz / BM);  // (50, 32)
    const int xsplit = G3H / BN;                // 18

    // Precompute: G_cls = cls @ w_ih^T + b_ih
    split_kernel<<<(BH + 255) / 256, 256>>>(cls, p_a_hi, p_a_lo, BH);
    gemm_f16x2<<<gGates, 256, GEMM_SMEM>>>(p_a_hi, p_a_lo, p_wih_hi, p_wih_lo,
                                           b_ih, p_Gcls, G3H, Hsz);
    // Precompute: AE_proj = ae_w @ w_ih^T
    split_kernel<<<(NHW + 255) / 256, 256>>>(ae_w, p_a_hi, p_a_lo, NHW);
    gemm_f16x2<<<gGates, 256, GEMM_SMEM>>>(p_a_hi, p_a_lo, p_wih_hi, p_wih_lo,
                                           nullptr, p_AEp, G3H, Hsz);

    // Step 0 (h + its fp16 split written by gru_step0)
    gru_step0_kernel<<<(BH + 255) / 256, 256>>>(b_hh, BH);

    for (int j = 0; j < Lsz; j++) {
        if (j < Lsz - 1) {
            gemm_f16x2_dual<<<gDual, 256, GEMM_SMEM>>>(
                p_a_hi, p_a_lo,
                p_whh_hi, p_whh_lo, b_hh, p_gh, G3H,
                p_hw_hi, p_hw_lo, head_b, p_logits, Asz, Hsz, xsplit);
        } else {
            gemm_f16x2<<<gHead, 256, GEMM_SMEM>>>(p_a_hi, p_a_lo, p_hw_hi, p_hw_lo,
                                                  head_b, p_logits, Asz, Hsz);
        }
        select_step_kernel<<<Bsz, 256>>>(x_, out, j, sub[j][0], sub[j][1]);
        if (j < Lsz - 1)
            gru_step_kernel<<<(BH + 255) / 256, 256>>>(j + 1, BH);
    }
}